// round 12
// baseline (speedup 1.0000x reference)
#include <cuda_runtime.h>
#include <cuda_bf16.h>
#include <mma.h>
#include <cstdint>
#include <math.h>

using namespace nvcuda;

#define BB 2
#define CC 128
#define HH 128
#define WW 128
#define NPIX (HH*WW)
#define HTH 184
#define HTW 180
#define NBINS (HTH*HTW)
#define NSPH 16384
#define KHT 8
#define KSPH 16
#define NN0 1024
#define NN1 256
#define NN2 64
#define EPS_F 1e-5f
#define M_CONV (BB*NBINS)       // 66240 = 1035 * 64
#define NCHUNK 240
#define ROWS_PER_CHUNK (M_CONV/NCHUNK)

// ================= scratch (static device memory) =================
__device__ float g_xt[BB*NPIX*CC];
__device__ __align__(16) __nv_bfloat16 g_htb_hi[BB*NBINS*CC];
__device__ __align__(16) __nv_bfloat16 g_htb_lo[BB*NBINS*CC];
__device__ __align__(16) __nv_bfloat16 g_wb_hi[1152*128];   // weights [k][n] (native layout)
__device__ __align__(16) __nv_bfloat16 g_wb_lo[1152*128];
__device__ float g_hc[BB*NBINS*CC];
__device__ float g_scale[CC], g_bias[CC];
__device__ float g_cscale[CC], g_cbias[CC];
__device__ float g_psum[NCHUNK*CC], g_psq[NCHUNK*CC];
__device__ float g_s0[BB*NN0*CC], g_s1[BB*3*NN1*CC], g_s2[BB*3*NN2*CC];
__device__ float g_y0[BB*NN0*64], g_y1[BB*3*NN1*64], g_y2[BB*3*NN2*64];
__device__ float g_tmp[BB*NN0*64];
__device__ float g_z[BB*NN0*128];
__device__ float g_scs[64], g_scb[64];
__device__ float g_p2s[32*64], g_p2q[32*64];
__device__ float g_logit[BB*NN0 + BB*3*NN1 + BB*3*NN2];

// ================= 1) image BN stats =================
__global__ void k_img_stats(const float* __restrict__ img,
                            const float* __restrict__ gamma,
                            const float* __restrict__ beta) {
    int c = blockIdx.x;
    float s = 0.f, q = 0.f;
    for (int i = threadIdx.x; i < BB*NPIX; i += blockDim.x) {
        int b = i >> 14;
        int p = i & (NPIX-1);
        float v = img[(b*CC + c)*NPIX + p];
        s += v; q += v*v;
    }
    __shared__ float ss[256], sq[256];
    ss[threadIdx.x] = s; sq[threadIdx.x] = q;
    __syncthreads();
    for (int st = 128; st > 0; st >>= 1) {
        if (threadIdx.x < st) { ss[threadIdx.x] += ss[threadIdx.x+st]; sq[threadIdx.x] += sq[threadIdx.x+st]; }
        __syncthreads();
    }
    if (threadIdx.x == 0) {
        float inv = 1.f/(BB*NPIX);
        float m = ss[0]*inv;
        float var = sq[0]*inv - m*m;
        float r = rsqrtf(var + EPS_F);
        g_scale[c] = gamma[c]*r;
        g_bias[c]  = beta[c] - gamma[c]*m*r;
    }
}

// ================= 2) BN + ReLU + transpose =================
__global__ void k_bn_transpose(const float* __restrict__ img) {
    __shared__ float tile[32][33];
    int p0 = blockIdx.x*32, c0 = blockIdx.y*32, b = blockIdx.z;
    #pragma unroll
    for (int j = 0; j < 4; j++) {
        int c = c0 + threadIdx.y + j*8;
        tile[threadIdx.y + j*8][threadIdx.x] = img[(b*CC + c)*NPIX + p0 + threadIdx.x];
    }
    __syncthreads();
    #pragma unroll
    for (int j = 0; j < 4; j++) {
        int p = p0 + threadIdx.y + j*8;
        int c = c0 + threadIdx.x;
        float v = g_scale[c]*tile[threadIdx.x][threadIdx.y + j*8] + g_bias[c];
        g_xt[((size_t)b*NPIX + p)*CC + c] = fmaxf(v, 0.f);
    }
}

// ================= 3) Hough gather -> bf16 hi/lo split =================
__global__ void k_hough(const int* __restrict__ ht_idx, const float* __restrict__ ht_w) {
    int bin = blockIdx.x, b = blockIdx.y, c = threadIdx.x;
    const float* xb = g_xt + (size_t)b*NPIX*CC;
    float acc = 0.f;
    #pragma unroll
    for (int k = 0; k < KHT; k++) {
        int p = __ldg(&ht_idx[bin*KHT + k]);
        float w = __ldg(&ht_w[bin*KHT + k]);
        acc += w * xb[p*CC + c];
    }
    size_t idx = ((size_t)b*NBINS + bin)*CC + c;
    __nv_bfloat16 hi = __float2bfloat16(acc);
    float rem = acc - __bfloat162float(hi);
    g_htb_hi[idx] = hi;
    g_htb_lo[idx] = __float2bfloat16(rem);
}

// ================= 3b) weight bf16 split (layout already [k][n]) =================
__global__ void k_wsplit(const float* __restrict__ w) {
    int i = blockIdx.x*256 + threadIdx.x;
    if (i >= 1152*128) return;
    float v = w[i];
    __nv_bfloat16 hi = __float2bfloat16(v);
    float rem = v - __bfloat162float(hi);
    g_wb_hi[i] = hi;
    g_wb_lo[i] = __float2bfloat16(rem);
}

// ================= 4) 3x3 conv via wmma bf16-split (HMMA tensor cores) =================
// D[66240,128] = A[66240,1152] * B[1152,128], 72 K-chunks of 16.
// 3 accumulate passes per chunk: Ahi*Bhi + Ahi*Blo + Alo*Bhi  (lo*lo ~2^-32, dropped)
#define BM 64
#define BN 128
#define BK 16
#define AKLD 24   // padded ld for A tiles (multiple of 8, kills 32B-row conflicts)
__global__ void __launch_bounds__(256) k_conv_wmma() {
    __shared__ __nv_bfloat16 Ah[BM][AKLD];
    __shared__ __nv_bfloat16 Al[BM][AKLD];
    __shared__ __nv_bfloat16 Bh[BK][BN];
    __shared__ __nv_bfloat16 Bl[BK][BN];

    int tid = threadIdx.x;
    int warp = tid >> 5;
    int wm = warp >> 1;          // 0..3 -> M offset wm*16
    int wn = warp & 1;           // 0..1 -> N offset wn*64
    int m0 = blockIdx.x*BM;

    wmma::fragment<wmma::accumulator, 16, 16, 16, float> cfrag[4];
    #pragma unroll
    for (int f = 0; f < 4; f++) wmma::fill_fragment(cfrag[f], 0.f);

    // A loader: row lm (0..63), k-segment lseg (0,4,8,12)
    int lm = tid >> 2, lseg = (tid & 3)*4;
    int s  = m0 + lm;
    int sb = s / NBINS; int sr = s - sb*NBINS;
    int sh = sr / HTW;  int sw = sr - sh*HTW;
    // B loader: k-row lkb (0..15), n-col lcb (0,8,...,120)
    int lkb = tid >> 4, lcb = (tid & 15)*8;

    for (int ch = 0; ch < 72; ch++) {
        int r = ch >> 3, kk = (ch & 7)*BK;
        int ry = r/3;
        int dy = ry - 1, dx = r - ry*3 - 1;
        int h2 = sh + dy, w2 = sw + dx;
        bool valid = ((unsigned)h2 < HTH) && ((unsigned)w2 < HTW);

        uint2 vh = make_uint2(0u, 0u), vl = make_uint2(0u, 0u);
        if (valid) {
            size_t a = ((size_t)sb*NBINS + (size_t)h2*HTW + w2)*128 + kk + lseg;
            vh = *(const uint2*)(g_htb_hi + a);
            vl = *(const uint2*)(g_htb_lo + a);
        }
        *(uint2*)&Ah[lm][lseg] = vh;
        *(uint2*)&Al[lm][lseg] = vl;

        size_t bofs = (size_t)(r*128 + kk + lkb)*128 + lcb;
        *(uint4*)&Bh[lkb][lcb] = *(const uint4*)(g_wb_hi + bofs);
        *(uint4*)&Bl[lkb][lcb] = *(const uint4*)(g_wb_lo + bofs);
        __syncthreads();

        wmma::fragment<wmma::matrix_a, 16, 16, 16, __nv_bfloat16, wmma::row_major> afh, afl;
        wmma::load_matrix_sync(afh, &Ah[wm*16][0], AKLD);
        wmma::load_matrix_sync(afl, &Al[wm*16][0], AKLD);
        #pragma unroll
        for (int f = 0; f < 4; f++) {
            int n0 = wn*64 + f*16;
            wmma::fragment<wmma::matrix_b, 16, 16, 16, __nv_bfloat16, wmma::row_major> bfh, bfl;
            wmma::load_matrix_sync(bfh, &Bh[0][n0], BN);
            wmma::load_matrix_sync(bfl, &Bl[0][n0], BN);
            wmma::mma_sync(cfrag[f], afh, bfh, cfrag[f]);
            wmma::mma_sync(cfrag[f], afh, bfl, cfrag[f]);
            wmma::mma_sync(cfrag[f], afl, bfh, cfrag[f]);
        }
        __syncthreads();
    }

    #pragma unroll
    for (int f = 0; f < 4; f++) {
        int mrow = m0 + wm*16;
        int ncol = wn*64 + f*16;
        wmma::store_matrix_sync(g_hc + (size_t)mrow*128 + ncol, cfrag[f], 128, wmma::mem_row_major);
    }
}

// ================= 5) conv BN stats =================
__global__ void k_conv_stats1() {
    int chunk = blockIdx.x, c = threadIdx.x;
    size_t r0 = (size_t)chunk * ROWS_PER_CHUNK;
    float s = 0.f, q = 0.f;
    for (int i = 0; i < ROWS_PER_CHUNK; i++) {
        float v = g_hc[(r0 + i)*CC + c];
        s += v; q += v*v;
    }
    g_psum[chunk*CC + c] = s;
    g_psq[chunk*CC + c]  = q;
}
__global__ void k_conv_stats2(const float* __restrict__ gamma, const float* __restrict__ beta) {
    int c = threadIdx.x;
    float s = 0.f, q = 0.f;
    for (int i = 0; i < NCHUNK; i++) { s += g_psum[i*CC + c]; q += g_psq[i*CC + c]; }
    float inv = 1.f/(float)M_CONV;
    float m = s*inv;
    float var = q*inv - m*m;
    float r = rsqrtf(var + EPS_F);
    g_cscale[c] = gamma[c]*r;
    g_cbias[c]  = beta[c] - gamma[c]*m*r;
}

// ================= 6) sphere gather =================
__global__ void k_sphere(const int* __restrict__ ind, const int* __restrict__ sph_idx,
                         const float* __restrict__ sph_w, float* __restrict__ out, int S) {
    int j = blockIdx.x, b = blockIdx.y, c = threadIdx.x;
    int v = __ldg(&ind[b*S + j]);
    const float* hc = g_hc + (size_t)b*NBINS*CC;
    float sc = g_cscale[c], bi = g_cbias[c];
    float acc = 0.f;
    #pragma unroll
    for (int k = 0; k < KSPH; k++) {
        int bin = __ldg(&sph_idx[v*KSPH + k]);
        float w = __ldg(&sph_w[v*KSPH + k]);
        float x = sc*hc[(size_t)bin*CC + c] + bi;
        acc += w * fmaxf(x, 0.f);
    }
    out[((size_t)b*S + j)*CC + c] = acc;
}

// ================= 7) sconv =================
__global__ void __launch_bounds__(256) k_sconv2(const float* __restrict__ x,
                                                const float* __restrict__ w,
                                                const float* __restrict__ bias,
                                                float* __restrict__ y) {
    __shared__ float Ws[128][64];
    __shared__ float xr[4][128];
    __shared__ float bs[64];
    int tid = threadIdx.x;
    for (int i = tid; i < 64*128; i += 256) {
        int o = i >> 7, c = i & 127;
        Ws[c][o] = w[i];
    }
    if (tid < 64) bs[tid] = bias[tid];
    __syncthreads();
    int ty = tid >> 6, o = tid & 63;
    int m0 = blockIdx.x * 16;
    for (int rr = 0; rr < 16; rr += 4) {
        int m = m0 + rr + ty;
        xr[ty][o]      = x[(size_t)m*128 + o];
        xr[ty][64 + o] = x[(size_t)m*128 + 64 + o];
        __syncthreads();
        float acc = bs[o];
        #pragma unroll 8
        for (int c = 0; c < 128; c++) acc += xr[ty][c]*Ws[c][o];
        y[(size_t)m*64 + o] = acc;
        __syncthreads();
    }
}

// ================= 7b) sconv BN stats =================
__global__ void k_sc_stats1(const float* __restrict__ y) {
    int chunk = blockIdx.x, o = threadIdx.x;
    size_t r0 = (size_t)chunk * 64;
    float s = 0.f, q = 0.f;
    for (int i = 0; i < 64; i++) {
        float v = y[(r0 + i)*64 + o];
        s += v; q += v*v;
    }
    g_p2s[chunk*64 + o] = s;
    g_p2q[chunk*64 + o] = q;
}
__global__ void k_sc_stats2(const float* __restrict__ gamma, const float* __restrict__ beta,
                            int nchunk, int M) {
    int o = threadIdx.x;
    float s = 0.f, q = 0.f;
    for (int i = 0; i < nchunk; i++) { s += g_p2s[i*64 + o]; q += g_p2q[i*64 + o]; }
    float inv = 1.f/(float)M;
    float mn = s*inv;
    float var = q*inv - mn*mn;
    float r = rsqrtf(var + EPS_F);
    g_scs[o] = gamma[o]*r;
    g_scb[o] = beta[o] - gamma[o]*mn*r;
}

// ================= 8) EdgeConv GEMM =================
__global__ void __launch_bounds__(256) k_dgcn_gemm(const float* __restrict__ x,
                                                   const float* __restrict__ W,
                                                   const float* __restrict__ bias,
                                                   const float* __restrict__ bnsc,
                                                   const float* __restrict__ bnbi,
                                                   float* __restrict__ z) {
    __shared__ float Wc[64][64];
    __shared__ float Wn[64][64];
    __shared__ float xr[4][64];
    __shared__ float bs[64];
    int tid = threadIdx.x;
    for (int i = tid; i < 64*64; i += 256) {
        int c = i >> 6, o = i & 63;
        float wt = W[c*64 + o], wb = W[(64 + c)*64 + o];
        Wc[c][o] = wt - wb;
        Wn[c][o] = wb;
    }
    if (tid < 64) bs[tid] = bias[tid];
    __syncthreads();
    int ty = tid >> 6, o = tid & 63;
    int m0 = blockIdx.x * 16;
    for (int rr = 0; rr < 16; rr += 4) {
        int m = m0 + rr + ty;
        float v = x[(size_t)m*64 + o];
        if (bnsc) v = fmaxf(bnsc[o]*v + bnbi[o], 0.f);
        xr[ty][o] = v;
        __syncthreads();
        float a0 = bs[o], a1 = 0.f;
        #pragma unroll 8
        for (int c = 0; c < 64; c++) {
            float xv = xr[ty][c];
            a0 += xv * Wc[c][o];
            a1 += xv * Wn[c][o];
        }
        z[(size_t)m*128 + o]      = a0;
        z[(size_t)m*128 + 64 + o] = a1;
        __syncthreads();
    }
}

// ================= 8b) EdgeConv combine =================
__global__ void k_dgcn_combine(const float* __restrict__ z, const int* __restrict__ edge,
                               float* __restrict__ xo, int n, int kn) {
    int bg = blockIdx.y;
    int o  = threadIdx.x & 63;
    int jy = threadIdx.x >> 6;
    int j  = blockIdx.x*4 + jy;
    const int* ec = edge + (size_t)bg*2*n*kn;
    const int* en = ec + n*kn;
    const float* zb = z + (size_t)bg*n*128;
    int e0 = j*kn;
    float mx = 0.f;
    for (int kk = 0; kk < kn; kk++) {
        int ci = __ldg(&ec[e0 + kk]);
        int ni = __ldg(&en[e0 + kk]);
        float v = zb[(size_t)ci*128 + o] + zb[(size_t)ni*128 + 64 + o];
        mx = fmaxf(mx, fmaxf(v, 0.f));
    }
    xo[((size_t)bg*n + j)*64 + o] = mx;
}

// ================= 9) head =================
__global__ void k_head(const float* __restrict__ x, const float* __restrict__ hw,
                       const float* __restrict__ hb, float* __restrict__ logit, int total) {
    int gw = (blockIdx.x*blockDim.x + threadIdx.x) >> 5;
    int lane = threadIdx.x & 31;
    if (gw >= total) return;
    float a = x[(size_t)gw*64 + lane]*hw[lane] + x[(size_t)gw*64 + 32 + lane]*hw[32 + lane];
    #pragma unroll
    for (int s2 = 16; s2 > 0; s2 >>= 1) a += __shfl_down_sync(0xffffffffu, a, s2);
    if (lane == 0) logit[gw] = a + hb[0];
}

// ================= 10) BCE =================
__global__ void k_bce(const float* __restrict__ logit, const int* __restrict__ target,
                      float* __restrict__ out, int M, int outIdx) {
    float sp = 0.f, sn = 0.f, cp = 0.f, cn = 0.f;
    for (int i = threadIdx.x; i < M; i += 256) {
        float z = logit[i];
        float t = (float)target[i];
        float l = fmaxf(z, 0.f) - z*t + log1pf(expf(-fabsf(z)));
        if (t > 0.5f) { sp += l; cp += 1.f; } else { sn += l; cn += 1.f; }
    }
    __shared__ float r0[256], r1[256], r2[256], r3[256];
    r0[threadIdx.x]=sp; r1[threadIdx.x]=sn; r2[threadIdx.x]=cp; r3[threadIdx.x]=cn;
    __syncthreads();
    for (int st = 128; st > 0; st >>= 1) {
        if (threadIdx.x < st) {
            r0[threadIdx.x]+=r0[threadIdx.x+st]; r1[threadIdx.x]+=r1[threadIdx.x+st];
            r2[threadIdx.x]+=r2[threadIdx.x+st]; r3[threadIdx.x]+=r3[threadIdx.x+st];
        }
        __syncthreads();
    }
    if (threadIdx.x == 0) {
        out[outIdx]   = r0[0] / fmaxf(r2[0], 1.f);
        out[outIdx+1] = r1[0] / fmaxf(r3[0], 1.f);
    }
}

// ================= 11) preds =================
__global__ void k_preds(float* __restrict__ out) {
    int i = blockIdx.x*blockDim.x + threadIdx.x;
    if (i >= 3968) return;
    float z; int b, col;
    if (i < 2048) {
        b = i >> 10; col = i & 1023;
        z = g_logit[i];
    } else if (i < 3584) {
        int m = i - 2048;
        int bg = m >> 8, j = m & 255;
        b = bg/3; int v = bg - b*3;
        col = 1024 + v*256 + j;
        z = g_logit[2048 + m];
    } else {
        int m = i - 3584;
        int bg = m >> 6, j = m & 63;
        b = bg/3; int v = bg - b*3;
        col = 1792 + v*64 + j;
        z = g_logit[3584 + m];
    }
    out[6 + b*1984 + col] = 1.f/(1.f + expf(-z));
}

// ================= launch =================
extern "C" void kernel_launch(void* const* d_in, const int* in_sizes, int n_in,
                              void* d_out, int out_size) {
    const float* image     = (const float*)d_in[0];
    const float* bn_gamma  = (const float*)d_in[1];
    const float* bn_beta   = (const float*)d_in[2];
    const int*   ht_idx    = (const int*)  d_in[3];
    const float* ht_w      = (const float*)d_in[4];
    const float* w_htconv  = (const float*)d_in[5];
    const float* htbn_g    = (const float*)d_in[6];
    const float* htbn_b    = (const float*)d_in[7];
    const int*   sph_idx   = (const int*)  d_in[8];
    const float* sph_w     = (const float*)d_in[9];
    const float* w_sc      = (const float*)d_in[10];
    const float* b_sc      = (const float*)d_in[11];
    const float* scbn_g    = (const float*)d_in[12];
    const float* scbn_b    = (const float*)d_in[13];
    const float* dgcn_w    = (const float*)d_in[14];
    const float* dgcn_b    = (const float*)d_in[15];
    const float* dgcn_hw   = (const float*)d_in[16];
    const float* dgcn_hb   = (const float*)d_in[17];
    const int*   ind0      = (const int*)  d_in[18];
    const int*   ind1      = (const int*)  d_in[19];
    const int*   ind2      = (const int*)  d_in[20];
    const int*   edge0     = (const int*)  d_in[21];
    const int*   edge1     = (const int*)  d_in[22];
    const int*   edge2     = (const int*)  d_in[23];
    const int*   target0   = (const int*)  d_in[24];
    const int*   target1   = (const int*)  d_in[25];
    const int*   target2   = (const int*)  d_in[26];
    float* out = (float*)d_out;

    k_img_stats<<<CC, 256>>>(image, bn_gamma, bn_beta);
    k_bn_transpose<<<dim3(NPIX/32, CC/32, BB), dim3(32,8)>>>(image);
    k_wsplit<<<(1152*128 + 255)/256, 256>>>(w_htconv);
    k_hough<<<dim3(NBINS, BB), CC>>>(ht_idx, ht_w);
    k_conv_wmma<<<M_CONV/BM, 256>>>();
    k_conv_stats1<<<NCHUNK, CC>>>();
    k_conv_stats2<<<1, CC>>>(htbn_g, htbn_b);

    float* g_s0p; cudaGetSymbolAddress((void**)&g_s0p, g_s0);
    float* g_s1p; cudaGetSymbolAddress((void**)&g_s1p, g_s1);
    float* g_s2p; cudaGetSymbolAddress((void**)&g_s2p, g_s2);
    float* g_y0p; cudaGetSymbolAddress((void**)&g_y0p, g_y0);
    float* g_y1p; cudaGetSymbolAddress((void**)&g_y1p, g_y1);
    float* g_y2p; cudaGetSymbolAddress((void**)&g_y2p, g_y2);
    float* g_tmpp; cudaGetSymbolAddress((void**)&g_tmpp, g_tmp);
    float* g_zp; cudaGetSymbolAddress((void**)&g_zp, g_z);
    float* g_scsp; cudaGetSymbolAddress((void**)&g_scsp, g_scs);
    float* g_scbp; cudaGetSymbolAddress((void**)&g_scbp, g_scb);
    float* g_logitp; cudaGetSymbolAddress((void**)&g_logitp, g_logit);

    k_sphere<<<dim3(NN0,   BB), CC>>>(ind0, sph_idx, sph_w, g_s0p, NN0);
    k_sphere<<<dim3(3*NN1, BB), CC>>>(ind1, sph_idx, sph_w, g_s1p, 3*NN1);
    k_sphere<<<dim3(3*NN2, BB), CC>>>(ind2, sph_idx, sph_w, g_s2p, 3*NN2);

    const int M0 = BB*NN0, M1 = BB*3*NN1, M2 = BB*3*NN2;
    const float* srcS[3] = {g_s0p, g_s1p, g_s2p};
    float* ybuf[3] = {g_y0p, g_y1p, g_y2p};
    const int Ms[3] = {M0, M1, M2};

    for (int s = 0; s < 3; s++) {
        int M = Ms[s];
        k_sconv2<<<M/16, 256>>>(srcS[s], w_sc + (size_t)s*64*128, b_sc + s*64, ybuf[s]);
        k_sc_stats1<<<M/64, 64>>>(ybuf[s]);
        k_sc_stats2<<<1, 64>>>(scbn_g + s*64, scbn_b + s*64, M/64, M);

        int n  = (s == 0) ? NN0 : ((s == 1) ? NN1 : NN2);
        int bg = (s == 0) ? BB : BB*3;
        const int* eg = (s == 0) ? edge0 : ((s == 1) ? edge1 : edge2);
        float* xin = ybuf[s];
        for (int L = 0; L < 4; L++) {
            float* xout = (L & 1) ? ybuf[s] : g_tmpp;
            k_dgcn_gemm<<<M/16, 256>>>(xin,
                dgcn_w + ((size_t)s*4 + L)*128*64,
                dgcn_b + ((size_t)s*4 + L)*64,
                (L == 0) ? g_scsp : (const float*)0,
                (L == 0) ? g_scbp : (const float*)0,
                g_zp);
            k_dgcn_combine<<<dim3(n/4, bg), 256>>>(g_zp, eg, xout, n, 8);
            xin = xout;
        }
        int off = (s == 0) ? 0 : ((s == 1) ? M0 : M0 + M1);
        k_head<<<(M*32 + 255)/256, 256>>>(xin, dgcn_hw + s*64, dgcn_hb + s, g_logitp + off, M);
    }

    k_bce<<<1, 256>>>(g_logitp,           target0, out, M0, 0);
    k_bce<<<1, 256>>>(g_logitp + M0,      target1, out, M1, 2);
    k_bce<<<1, 256>>>(g_logitp + M0 + M1, target2, out, M2, 4);
    k_preds<<<(3968 + 255)/256, 256>>>(out);
    (void)in_sizes; (void)n_in; (void)out_size;
}

// round 15
// speedup vs baseline: 1.4778x; 1.4778x over previous
#include <cuda_runtime.h>
#include <cuda_bf16.h>
#include <mma.h>
#include <cstdint>
#include <math.h>

using namespace nvcuda;

#define BB 2
#define CC 128
#define HH 128
#define WW 128
#define NPIX (HH*WW)
#define HTH 184
#define HTW 180
#define NBINS (HTH*HTW)
#define NSPH 16384
#define KHT 8
#define KSPH 16
#define NN0 1024
#define NN1 256
#define NN2 64
#define EPS_F 1e-5f
#define M_CONV (BB*NBINS)       // 66240
#define NCHUNK 240
#define ROWS_PER_CHUNK (M_CONV/NCHUNK)

// conv tiling
#define CBM 128
#define CLD 136                  // padded ld in elements (+16B per row)
#define CONV_GRID ((M_CONV + CBM - 1)/CBM)   // 518
#define CONV_SMEM (4*128*CLD*2)  // Ah,Al,Bh,Bl bf16 = 139264 B

// ================= scratch (static device memory) =================
__device__ float g_xt[BB*NPIX*CC];
__device__ __align__(16) __nv_bfloat16 g_htb_hi[BB*NBINS*CC];
__device__ __align__(16) __nv_bfloat16 g_htb_lo[BB*NBINS*CC];
__device__ __align__(16) __nv_bfloat16 g_wb_hi[1152*128];   // weights [k][n] native
__device__ __align__(16) __nv_bfloat16 g_wb_lo[1152*128];
__device__ float g_hc[BB*NBINS*CC];
__device__ float g_scale[CC], g_bias[CC];
__device__ float g_cscale[CC], g_cbias[CC];
__device__ float g_psum[NCHUNK*CC], g_psq[NCHUNK*CC];
__device__ float g_s0[BB*NN0*CC], g_s1[BB*3*NN1*CC], g_s2[BB*3*NN2*CC];
__device__ float g_y0[BB*NN0*64], g_y1[BB*3*NN1*64], g_y2[BB*3*NN2*64];
__device__ float g_tmp[BB*NN0*64];
__device__ float g_z[BB*NN0*128];
__device__ float g_scs[64], g_scb[64];
__device__ float g_p2s[32*64], g_p2q[32*64];
__device__ float g_logit[BB*NN0 + BB*3*NN1 + BB*3*NN2];

// ================= 1) image BN stats =================
__global__ void k_img_stats(const float* __restrict__ img,
                            const float* __restrict__ gamma,
                            const float* __restrict__ beta) {
    int c = blockIdx.x;
    float s = 0.f, q = 0.f;
    for (int i = threadIdx.x; i < BB*NPIX; i += blockDim.x) {
        int b = i >> 14;
        int p = i & (NPIX-1);
        float v = img[(b*CC + c)*NPIX + p];
        s += v; q += v*v;
    }
    __shared__ float ss[256], sq[256];
    ss[threadIdx.x] = s; sq[threadIdx.x] = q;
    __syncthreads();
    for (int st = 128; st > 0; st >>= 1) {
        if (threadIdx.x < st) { ss[threadIdx.x] += ss[threadIdx.x+st]; sq[threadIdx.x] += sq[threadIdx.x+st]; }
        __syncthreads();
    }
    if (threadIdx.x == 0) {
        float inv = 1.f/(BB*NPIX);
        float m = ss[0]*inv;
        float var = sq[0]*inv - m*m;
        float r = rsqrtf(var + EPS_F);
        g_scale[c] = gamma[c]*r;
        g_bias[c]  = beta[c] - gamma[c]*m*r;
    }
}

// ================= 2) BN + ReLU + transpose =================
__global__ void k_bn_transpose(const float* __restrict__ img) {
    __shared__ float tile[32][33];
    int p0 = blockIdx.x*32, c0 = blockIdx.y*32, b = blockIdx.z;
    #pragma unroll
    for (int j = 0; j < 4; j++) {
        int c = c0 + threadIdx.y + j*8;
        tile[threadIdx.y + j*8][threadIdx.x] = img[(b*CC + c)*NPIX + p0 + threadIdx.x];
    }
    __syncthreads();
    #pragma unroll
    for (int j = 0; j < 4; j++) {
        int p = p0 + threadIdx.y + j*8;
        int c = c0 + threadIdx.x;
        float v = g_scale[c]*tile[threadIdx.x][threadIdx.y + j*8] + g_bias[c];
        g_xt[((size_t)b*NPIX + p)*CC + c] = fmaxf(v, 0.f);
    }
}

// ================= 3) Hough gather -> bf16 hi/lo split =================
__global__ void k_hough(const int* __restrict__ ht_idx, const float* __restrict__ ht_w) {
    int bin = blockIdx.x, b = blockIdx.y, c = threadIdx.x;
    const float* xb = g_xt + (size_t)b*NPIX*CC;
    float acc = 0.f;
    #pragma unroll
    for (int k = 0; k < KHT; k++) {
        int p = __ldg(&ht_idx[bin*KHT + k]);
        float w = __ldg(&ht_w[bin*KHT + k]);
        acc += w * xb[p*CC + c];
    }
    size_t idx = ((size_t)b*NBINS + bin)*CC + c;
    __nv_bfloat16 hi = __float2bfloat16(acc);
    float rem = acc - __bfloat162float(hi);
    g_htb_hi[idx] = hi;
    g_htb_lo[idx] = __float2bfloat16(rem);
}

// ================= 3b) weight bf16 split (layout already [k][n]) =================
__global__ void k_wsplit(const float* __restrict__ w) {
    int i = blockIdx.x*256 + threadIdx.x;
    if (i >= 1152*128) return;
    float v = w[i];
    __nv_bfloat16 hi = __float2bfloat16(v);
    float rem = v - __bfloat162float(hi);
    g_wb_hi[i] = hi;
    g_wb_lo[i] = __float2bfloat16(rem);
}

// ================= 4) 3x3 conv via wmma bf16-split, full-tap staging =================
// D[66240,128] = A[66240,1152]*B[1152,128]. Per CTA: 128 rows. Per tap (9):
// stage A[128,128] + B[128,128] (hi+lo) in smem, then 8 k-steps of wmma.
// 3 passes: Ahi*Bhi + Alo*Bhi + Ahi*Blo  (lo*lo dropped).
__global__ void __launch_bounds__(256) k_conv_wmma() {
    extern __shared__ __nv_bfloat16 smc[];
    __nv_bfloat16* Ah = smc;
    __nv_bfloat16* Al = smc + 128*CLD;
    __nv_bfloat16* Bh = smc + 2*128*CLD;
    __nv_bfloat16* Bl = smc + 3*128*CLD;

    int tid = threadIdx.x;
    int warp = tid >> 5;
    int wm = warp >> 1;          // 0..3 -> M offset wm*32
    int wn = warp & 1;           // 0..1 -> N offset wn*64
    int m0 = blockIdx.x*CBM;

    wmma::fragment<wmma::accumulator, 16, 16, 16, float> cf[2][4];
    #pragma unroll
    for (int i = 0; i < 2; i++)
        #pragma unroll
        for (int f = 0; f < 4; f++) wmma::fill_fragment(cf[i][f], 0.f);

    // loaders: row = tid>>1 (0..127), half = tid&1 (64-ch half)
    int row = tid >> 1, half = tid & 1;
    int m = m0 + row;
    bool rv = (m < M_CONV);
    int sb = 0, sh = 0, sw = 0;
    if (rv) {
        sb = m / NBINS;
        int sr = m - sb*NBINS;
        sh = sr / HTW;
        sw = sr - sh*HTW;
    }

    for (int r = 0; r < 9; r++) {
        int ry = r/3;
        int dy = ry - 1, dx = r - ry*3 - 1;
        int h2 = sh + dy, w2 = sw + dx;
        bool valid = rv && ((unsigned)h2 < HTH) && ((unsigned)w2 < HTW);
        size_t aoff = 0;
        if (valid) aoff = ((size_t)sb*NBINS + (size_t)h2*HTW + w2)*128 + half*64;
        size_t boff = ((size_t)(r*128 + row))*128 + half*64;

        __syncthreads();   // previous tap's compute done before overwrite
        #pragma unroll
        for (int j = 0; j < 8; j++) {
            uint4 vh = make_uint4(0u,0u,0u,0u), vl = make_uint4(0u,0u,0u,0u);
            if (valid) {
                vh = *(const uint4*)(g_htb_hi + aoff + j*8);
                vl = *(const uint4*)(g_htb_lo + aoff + j*8);
            }
            int so = row*CLD + half*64 + j*8;
            *(uint4*)&Ah[so] = vh;
            *(uint4*)&Al[so] = vl;
            *(uint4*)&Bh[so] = *(const uint4*)(g_wb_hi + boff + j*8);
            *(uint4*)&Bl[so] = *(const uint4*)(g_wb_lo + boff + j*8);
        }
        __syncthreads();

        for (int ks = 0; ks < 8; ks++) {
            wmma::fragment<wmma::matrix_a, 16, 16, 16, __nv_bfloat16, wmma::row_major> a0h, a0l, a1h, a1l;
            wmma::load_matrix_sync(a0h, &Ah[(wm*32)*CLD + ks*16], CLD);
            wmma::load_matrix_sync(a1h, &Ah[(wm*32 + 16)*CLD + ks*16], CLD);
            wmma::load_matrix_sync(a0l, &Al[(wm*32)*CLD + ks*16], CLD);
            wmma::load_matrix_sync(a1l, &Al[(wm*32 + 16)*CLD + ks*16], CLD);
            #pragma unroll
            for (int f = 0; f < 4; f++) {
                int n0 = wn*64 + f*16;
                wmma::fragment<wmma::matrix_b, 16, 16, 16, __nv_bfloat16, wmma::row_major> bh, bl;
                wmma::load_matrix_sync(bh, &Bh[(ks*16)*CLD + n0], CLD);
                wmma::load_matrix_sync(bl, &Bl[(ks*16)*CLD + n0], CLD);
                wmma::mma_sync(cf[0][f], a0h, bh, cf[0][f]);
                wmma::mma_sync(cf[0][f], a0l, bh, cf[0][f]);
                wmma::mma_sync(cf[0][f], a0h, bl, cf[0][f]);
                wmma::mma_sync(cf[1][f], a1h, bh, cf[1][f]);
                wmma::mma_sync(cf[1][f], a1l, bh, cf[1][f]);
                wmma::mma_sync(cf[1][f], a1h, bl, cf[1][f]);
            }
        }
    }

    #pragma unroll
    for (int i = 0; i < 2; i++) {
        int mrow = m0 + wm*32 + i*16;
        if (mrow < M_CONV) {   // 16-aligned frags vs 64-aligned boundary: all-or-nothing
            #pragma unroll
            for (int f = 0; f < 4; f++) {
                int n0 = wn*64 + f*16;
                wmma::store_matrix_sync(g_hc + (size_t)mrow*128 + n0, cf[i][f], 128, wmma::mem_row_major);
            }
        }
    }
}

// ================= 5) conv BN stats =================
__global__ void k_conv_stats1() {
    int chunk = blockIdx.x, c = threadIdx.x;
    size_t r0 = (size_t)chunk * ROWS_PER_CHUNK;
    float s = 0.f, q = 0.f;
    for (int i = 0; i < ROWS_PER_CHUNK; i++) {
        float v = g_hc[(r0 + i)*CC + c];
        s += v; q += v*v;
    }
    g_psum[chunk*CC + c] = s;
    g_psq[chunk*CC + c]  = q;
}
__global__ void k_conv_stats2(const float* __restrict__ gamma, const float* __restrict__ beta) {
    int c = threadIdx.x;
    float s = 0.f, q = 0.f;
    for (int i = 0; i < NCHUNK; i++) { s += g_psum[i*CC + c]; q += g_psq[i*CC + c]; }
    float inv = 1.f/(float)M_CONV;
    float m = s*inv;
    float var = q*inv - m*m;
    float r = rsqrtf(var + EPS_F);
    g_cscale[c] = gamma[c]*r;
    g_cbias[c]  = beta[c] - gamma[c]*m*r;
}

// ================= 6) sphere gather =================
__global__ void k_sphere(const int* __restrict__ ind, const int* __restrict__ sph_idx,
                         const float* __restrict__ sph_w, float* __restrict__ out, int S) {
    int j = blockIdx.x, b = blockIdx.y, c = threadIdx.x;
    int v = __ldg(&ind[b*S + j]);
    const float* hc = g_hc + (size_t)b*NBINS*CC;
    float sc = g_cscale[c], bi = g_cbias[c];
    float acc = 0.f;
    #pragma unroll
    for (int k = 0; k < KSPH; k++) {
        int bin = __ldg(&sph_idx[v*KSPH + k]);
        float w = __ldg(&sph_w[v*KSPH + k]);
        float x = sc*hc[(size_t)bin*CC + c] + bi;
        acc += w * fmaxf(x, 0.f);
    }
    out[((size_t)b*S + j)*CC + c] = acc;
}

// ================= 7) sconv =================
__global__ void __launch_bounds__(256) k_sconv2(const float* __restrict__ x,
                                                const float* __restrict__ w,
                                                const float* __restrict__ bias,
                                                float* __restrict__ y) {
    __shared__ float Ws[128][64];
    __shared__ float xr[4][128];
    __shared__ float bs[64];
    int tid = threadIdx.x;
    for (int i = tid; i < 64*128; i += 256) {
        int o = i >> 7, c = i & 127;
        Ws[c][o] = w[i];
    }
    if (tid < 64) bs[tid] = bias[tid];
    __syncthreads();
    int ty = tid >> 6, o = tid & 63;
    int m0 = blockIdx.x * 16;
    for (int rr = 0; rr < 16; rr += 4) {
        int m = m0 + rr + ty;
        xr[ty][o]      = x[(size_t)m*128 + o];
        xr[ty][64 + o] = x[(size_t)m*128 + 64 + o];
        __syncthreads();
        float acc = bs[o];
        #pragma unroll 8
        for (int c = 0; c < 128; c++) acc += xr[ty][c]*Ws[c][o];
        y[(size_t)m*64 + o] = acc;
        __syncthreads();
    }
}

// ================= 7b) sconv BN stats =================
__global__ void k_sc_stats1(const float* __restrict__ y) {
    int chunk = blockIdx.x, o = threadIdx.x;
    size_t r0 = (size_t)chunk * 64;
    float s = 0.f, q = 0.f;
    for (int i = 0; i < 64; i++) {
        float v = y[(r0 + i)*64 + o];
        s += v; q += v*v;
    }
    g_p2s[chunk*64 + o] = s;
    g_p2q[chunk*64 + o] = q;
}
__global__ void k_sc_stats2(const float* __restrict__ gamma, const float* __restrict__ beta,
                            int nchunk, int M) {
    int o = threadIdx.x;
    float s = 0.f, q = 0.f;
    for (int i = 0; i < nchunk; i++) { s += g_p2s[i*64 + o]; q += g_p2q[i*64 + o]; }
    float inv = 1.f/(float)M;
    float mn = s*inv;
    float var = q*inv - mn*mn;
    float r = rsqrtf(var + EPS_F);
    g_scs[o] = gamma[o]*r;
    g_scb[o] = beta[o] - gamma[o]*mn*r;
}

// ================= 8) EdgeConv GEMM =================
__global__ void __launch_bounds__(256) k_dgcn_gemm(const float* __restrict__ x,
                                                   const float* __restrict__ W,
                                                   const float* __restrict__ bias,
                                                   const float* __restrict__ bnsc,
                                                   const float* __restrict__ bnbi,
                                                   float* __restrict__ z) {
    __shared__ float Wc[64][64];
    __shared__ float Wn[64][64];
    __shared__ float xr[4][64];
    __shared__ float bs[64];
    int tid = threadIdx.x;
    for (int i = tid; i < 64*64; i += 256) {
        int c = i >> 6, o = i & 63;
        float wt = W[c*64 + o], wb = W[(64 + c)*64 + o];
        Wc[c][o] = wt - wb;
        Wn[c][o] = wb;
    }
    if (tid < 64) bs[tid] = bias[tid];
    __syncthreads();
    int ty = tid >> 6, o = tid & 63;
    int m0 = blockIdx.x * 16;
    for (int rr = 0; rr < 16; rr += 4) {
        int m = m0 + rr + ty;
        float v = x[(size_t)m*64 + o];
        if (bnsc) v = fmaxf(bnsc[o]*v + bnbi[o], 0.f);
        xr[ty][o] = v;
        __syncthreads();
        float a0 = bs[o], a1 = 0.f;
        #pragma unroll 8
        for (int c = 0; c < 64; c++) {
            float xv = xr[ty][c];
            a0 += xv * Wc[c][o];
            a1 += xv * Wn[c][o];
        }
        z[(size_t)m*128 + o]      = a0;
        z[(size_t)m*128 + 64 + o] = a1;
        __syncthreads();
    }
}

// ================= 8b) EdgeConv combine =================
__global__ void k_dgcn_combine(const float* __restrict__ z, const int* __restrict__ edge,
                               float* __restrict__ xo, int n, int kn) {
    int bg = blockIdx.y;
    int o  = threadIdx.x & 63;
    int jy = threadIdx.x >> 6;
    int j  = blockIdx.x*4 + jy;
    const int* ec = edge + (size_t)bg*2*n*kn;
    const int* en = ec + n*kn;
    const float* zb = z + (size_t)bg*n*128;
    int e0 = j*kn;
    float mx = 0.f;
    for (int kk = 0; kk < kn; kk++) {
        int ci = __ldg(&ec[e0 + kk]);
        int ni = __ldg(&en[e0 + kk]);
        float v = zb[(size_t)ci*128 + o] + zb[(size_t)ni*128 + 64 + o];
        mx = fmaxf(mx, fmaxf(v, 0.f));
    }
    xo[((size_t)bg*n + j)*64 + o] = mx;
}

// ================= 9) head =================
__global__ void k_head(const float* __restrict__ x, const float* __restrict__ hw,
                       const float* __restrict__ hb, float* __restrict__ logit, int total) {
    int gw = (blockIdx.x*blockDim.x + threadIdx.x) >> 5;
    int lane = threadIdx.x & 31;
    if (gw >= total) return;
    float a = x[(size_t)gw*64 + lane]*hw[lane] + x[(size_t)gw*64 + 32 + lane]*hw[32 + lane];
    #pragma unroll
    for (int s2 = 16; s2 > 0; s2 >>= 1) a += __shfl_down_sync(0xffffffffu, a, s2);
    if (lane == 0) logit[gw] = a + hb[0];
}

// ================= 10) BCE =================
__global__ void k_bce(const float* __restrict__ logit, const int* __restrict__ target,
                      float* __restrict__ out, int M, int outIdx) {
    float sp = 0.f, sn = 0.f, cp = 0.f, cn = 0.f;
    for (int i = threadIdx.x; i < M; i += 256) {
        float z = logit[i];
        float t = (float)target[i];
        float l = fmaxf(z, 0.f) - z*t + log1pf(expf(-fabsf(z)));
        if (t > 0.5f) { sp += l; cp += 1.f; } else { sn += l; cn += 1.f; }
    }
    __shared__ float r0[256], r1[256], r2[256], r3[256];
    r0[threadIdx.x]=sp; r1[threadIdx.x]=sn; r2[threadIdx.x]=cp; r3[threadIdx.x]=cn;
    __syncthreads();
    for (int st = 128; st > 0; st >>= 1) {
        if (threadIdx.x < st) {
            r0[threadIdx.x]+=r0[threadIdx.x+st]; r1[threadIdx.x]+=r1[threadIdx.x+st];
            r2[threadIdx.x]+=r2[threadIdx.x+st]; r3[threadIdx.x]+=r3[threadIdx.x+st];
        }
        __syncthreads();
    }
    if (threadIdx.x == 0) {
        out[outIdx]   = r0[0] / fmaxf(r2[0], 1.f);
        out[outIdx+1] = r1[0] / fmaxf(r3[0], 1.f);
    }
}

// ================= 11) preds =================
__global__ void k_preds(float* __restrict__ out) {
    int i = blockIdx.x*blockDim.x + threadIdx.x;
    if (i >= 3968) return;
    float z; int b, col;
    if (i < 2048) {
        b = i >> 10; col = i & 1023;
        z = g_logit[i];
    } else if (i < 3584) {
        int m = i - 2048;
        int bg = m >> 8, j = m & 255;
        b = bg/3; int v = bg - b*3;
        col = 1024 + v*256 + j;
        z = g_logit[2048 + m];
    } else {
        int m = i - 3584;
        int bg = m >> 6, j = m & 63;
        b = bg/3; int v = bg - b*3;
        col = 1792 + v*64 + j;
        z = g_logit[3584 + m];
    }
    out[6 + b*1984 + col] = 1.f/(1.f + expf(-z));
}

// ================= launch =================
extern "C" void kernel_launch(void* const* d_in, const int* in_sizes, int n_in,
                              void* d_out, int out_size) {
    const float* image     = (const float*)d_in[0];
    const float* bn_gamma  = (const float*)d_in[1];
    const float* bn_beta   = (const float*)d_in[2];
    const int*   ht_idx    = (const int*)  d_in[3];
    const float* ht_w      = (const float*)d_in[4];
    const float* w_htconv  = (const float*)d_in[5];
    const float* htbn_g    = (const float*)d_in[6];
    const float* htbn_b    = (const float*)d_in[7];
    const int*   sph_idx   = (const int*)  d_in[8];
    const float* sph_w     = (const float*)d_in[9];
    const float* w_sc      = (const float*)d_in[10];
    const float* b_sc      = (const float*)d_in[11];
    const float* scbn_g    = (const float*)d_in[12];
    const float* scbn_b    = (const float*)d_in[13];
    const float* dgcn_w    = (const float*)d_in[14];
    const float* dgcn_b    = (const float*)d_in[15];
    const float* dgcn_hw   = (const float*)d_in[16];
    const float* dgcn_hb   = (const float*)d_in[17];
    const int*   ind0      = (const int*)  d_in[18];
    const int*   ind1      = (const int*)  d_in[19];
    const int*   ind2      = (const int*)  d_in[20];
    const int*   edge0     = (const int*)  d_in[21];
    const int*   edge1     = (const int*)  d_in[22];
    const int*   edge2     = (const int*)  d_in[23];
    const int*   target0   = (const int*)  d_in[24];
    const int*   target1   = (const int*)  d_in[25];
    const int*   target2   = (const int*)  d_in[26];
    float* out = (float*)d_out;

    cudaFuncSetAttribute(k_conv_wmma, cudaFuncAttributeMaxDynamicSharedMemorySize, CONV_SMEM);

    k_img_stats<<<CC, 256>>>(image, bn_gamma, bn_beta);
    k_bn_transpose<<<dim3(NPIX/32, CC/32, BB), dim3(32,8)>>>(image);
    k_wsplit<<<(1152*128 + 255)/256, 256>>>(w_htconv);
    k_hough<<<dim3(NBINS, BB), CC>>>(ht_idx, ht_w);
    k_conv_wmma<<<CONV_GRID, 256, CONV_SMEM>>>();
    k_conv_stats1<<<NCHUNK, CC>>>();
    k_conv_stats2<<<1, CC>>>(htbn_g, htbn_b);

    float* g_s0p; cudaGetSymbolAddress((void**)&g_s0p, g_s0);
    float* g_s1p; cudaGetSymbolAddress((void**)&g_s1p, g_s1);
    float* g_s2p; cudaGetSymbolAddress((void**)&g_s2p, g_s2);
    float* g_y0p; cudaGetSymbolAddress((void**)&g_y0p, g_y0);
    float* g_y1p; cudaGetSymbolAddress((void**)&g_y1p, g_y1);
    float* g_y2p; cudaGetSymbolAddress((void**)&g_y2p, g_y2);
    float* g_tmpp; cudaGetSymbolAddress((void**)&g_tmpp, g_tmp);
    float* g_zp; cudaGetSymbolAddress((void**)&g_zp, g_z);
    float* g_scsp; cudaGetSymbolAddress((void**)&g_scsp, g_scs);
    float* g_scbp; cudaGetSymbolAddress((void**)&g_scbp, g_scb);
    float* g_logitp; cudaGetSymbolAddress((void**)&g_logitp, g_logit);

    k_sphere<<<dim3(NN0,   BB), CC>>>(ind0, sph_idx, sph_w, g_s0p, NN0);
    k_sphere<<<dim3(3*NN1, BB), CC>>>(ind1, sph_idx, sph_w, g_s1p, 3*NN1);
    k_sphere<<<dim3(3*NN2, BB), CC>>>(ind2, sph_idx, sph_w, g_s2p, 3*NN2);

    const int M0 = BB*NN0, M1 = BB*3*NN1, M2 = BB*3*NN2;
    const float* srcS[3] = {g_s0p, g_s1p, g_s2p};
    float* ybuf[3] = {g_y0p, g_y1p, g_y2p};
    const int Ms[3] = {M0, M1, M2};

    for (int s = 0; s < 3; s++) {
        int M = Ms[s];
        k_sconv2<<<M/16, 256>>>(srcS[s], w_sc + (size_t)s*64*128, b_sc + s*64, ybuf[s]);
        k_sc_stats1<<<M/64, 64>>>(ybuf[s]);
        k_sc_stats2<<<1, 64>>>(scbn_g + s*64, scbn_b + s*64, M/64, M);

        int n  = (s == 0) ? NN0 : ((s == 1) ? NN1 : NN2);
        int bg = (s == 0) ? BB : BB*3;
        const int* eg = (s == 0) ? edge0 : ((s == 1) ? edge1 : edge2);
        float* xin = ybuf[s];
        for (int L = 0; L < 4; L++) {
            float* xout = (L & 1) ? ybuf[s] : g_tmpp;
            k_dgcn_gemm<<<M/16, 256>>>(xin,
                dgcn_w + ((size_t)s*4 + L)*128*64,
                dgcn_b + ((size_t)s*4 + L)*64,
                (L == 0) ? g_scsp : (const float*)0,
                (L == 0) ? g_scbp : (const float*)0,
                g_zp);
            k_dgcn_combine<<<dim3(n/4, bg), 256>>>(g_zp, eg, xout, n, 8);
            xin = xout;
        }
        int off = (s == 0) ? 0 : ((s == 1) ? M0 : M0 + M1);
        k_head<<<(M*32 + 255)/256, 256>>>(xin, dgcn_hw + s*64, dgcn_hb + s, g_logitp + off, M);
    }

    k_bce<<<1, 256>>>(g_logitp,           target0, out, M0, 0);
    k_bce<<<1, 256>>>(g_logitp + M0,      target1, out, M1, 2);
    k_bce<<<1, 256>>>(g_logitp + M0 + M1, target2, out, M2, 4);
    k_preds<<<(3968 + 255)/256, 256>>>(out);
    (void)in_sizes; (void)n_in; (void)out_size;
}

// round 16
// speedup vs baseline: 1.8022x; 1.2195x over previous
#include <cuda_runtime.h>
#include <cuda_bf16.h>
#include <mma.h>
#include <cstdint>
#include <math.h>

using namespace nvcuda;

#define BB 2
#define CC 128
#define HH 128
#define WW 128
#define NPIX (HH*WW)
#define HTH 184
#define HTW 180
#define NBINS (HTH*HTW)
#define NSPH 16384
#define KHT 8
#define KSPH 16
#define NN0 1024
#define NN1 256
#define NN2 64
#define EPS_F 1e-5f
#define M_CONV (BB*NBINS)       // 66240
#define NCHUNK 240
#define ROWS_PER_CHUNK (M_CONV/NCHUNK)
#define MTOT 3968               // 2048 + 1536 + 384 global DGCN rows

// conv tiling
#define CBM 128
#define CLD 136
#define CONV_GRID ((M_CONV + CBM - 1)/CBM)   // 518
#define CONV_SMEM (4*128*CLD*2)

// ================= scratch (static device memory) =================
__device__ float g_xt[BB*NPIX*CC];
__device__ __align__(16) __nv_bfloat16 g_htb_hi[BB*NBINS*CC];
__device__ __align__(16) __nv_bfloat16 g_htb_lo[BB*NBINS*CC];
__device__ __align__(16) __nv_bfloat16 g_wb_hi[1152*128];
__device__ __align__(16) __nv_bfloat16 g_wb_lo[1152*128];
__device__ float g_hc[BB*NBINS*CC];
__device__ float g_scale[CC], g_bias[CC];
__device__ float g_cscale[CC], g_cbias[CC];
__device__ float g_psum[NCHUNK*CC], g_psq[NCHUNK*CC];
__device__ float g_sall[MTOT*128];
__device__ float g_yall[MTOT*64];
__device__ float g_tall[MTOT*64];
__device__ float g_zall[MTOT*128];
__device__ float g_scs[3*64], g_scb[3*64];
__device__ float g_p2s[62*64], g_p2q[62*64];
__device__ float g_logit[MTOT];

__device__ __forceinline__ int scale_of(int m) {
    return m < 2048 ? 0 : (m < 3584 ? 1 : 2);
}

// ================= 1) image BN stats =================
__global__ void k_img_stats(const float* __restrict__ img,
                            const float* __restrict__ gamma,
                            const float* __restrict__ beta) {
    int c = blockIdx.x;
    float s = 0.f, q = 0.f;
    for (int i = threadIdx.x; i < BB*NPIX; i += blockDim.x) {
        int b = i >> 14;
        int p = i & (NPIX-1);
        float v = img[(b*CC + c)*NPIX + p];
        s += v; q += v*v;
    }
    __shared__ float ss[256], sq[256];
    ss[threadIdx.x] = s; sq[threadIdx.x] = q;
    __syncthreads();
    for (int st = 128; st > 0; st >>= 1) {
        if (threadIdx.x < st) { ss[threadIdx.x] += ss[threadIdx.x+st]; sq[threadIdx.x] += sq[threadIdx.x+st]; }
        __syncthreads();
    }
    if (threadIdx.x == 0) {
        float inv = 1.f/(BB*NPIX);
        float m = ss[0]*inv;
        float var = sq[0]*inv - m*m;
        float r = rsqrtf(var + EPS_F);
        g_scale[c] = gamma[c]*r;
        g_bias[c]  = beta[c] - gamma[c]*m*r;
    }
}

// ================= 2) BN + ReLU + transpose =================
__global__ void k_bn_transpose(const float* __restrict__ img) {
    __shared__ float tile[32][33];
    int p0 = blockIdx.x*32, c0 = blockIdx.y*32, b = blockIdx.z;
    #pragma unroll
    for (int j = 0; j < 4; j++) {
        int c = c0 + threadIdx.y + j*8;
        tile[threadIdx.y + j*8][threadIdx.x] = img[(b*CC + c)*NPIX + p0 + threadIdx.x];
    }
    __syncthreads();
    #pragma unroll
    for (int j = 0; j < 4; j++) {
        int p = p0 + threadIdx.y + j*8;
        int c = c0 + threadIdx.x;
        float v = g_scale[c]*tile[threadIdx.x][threadIdx.y + j*8] + g_bias[c];
        g_xt[((size_t)b*NPIX + p)*CC + c] = fmaxf(v, 0.f);
    }
}

// ================= 3) Hough gather -> bf16 hi/lo split =================
__global__ void k_hough(const int* __restrict__ ht_idx, const float* __restrict__ ht_w) {
    int bin = blockIdx.x, b = blockIdx.y, c = threadIdx.x;
    const float* xb = g_xt + (size_t)b*NPIX*CC;
    float acc = 0.f;
    #pragma unroll
    for (int k = 0; k < KHT; k++) {
        int p = __ldg(&ht_idx[bin*KHT + k]);
        float w = __ldg(&ht_w[bin*KHT + k]);
        acc += w * xb[p*CC + c];
    }
    size_t idx = ((size_t)b*NBINS + bin)*CC + c;
    __nv_bfloat16 hi = __float2bfloat16(acc);
    float rem = acc - __bfloat162float(hi);
    g_htb_hi[idx] = hi;
    g_htb_lo[idx] = __float2bfloat16(rem);
}

// ================= 3b) weight bf16 split =================
__global__ void k_wsplit(const float* __restrict__ w) {
    int i = blockIdx.x*256 + threadIdx.x;
    if (i >= 1152*128) return;
    float v = w[i];
    __nv_bfloat16 hi = __float2bfloat16(v);
    float rem = v - __bfloat162float(hi);
    g_wb_hi[i] = hi;
    g_wb_lo[i] = __float2bfloat16(rem);
}

// ================= 4) 3x3 conv via wmma bf16-split, full-tap staging =================
__global__ void __launch_bounds__(256) k_conv_wmma() {
    extern __shared__ __nv_bfloat16 smc[];
    __nv_bfloat16* Ah = smc;
    __nv_bfloat16* Al = smc + 128*CLD;
    __nv_bfloat16* Bh = smc + 2*128*CLD;
    __nv_bfloat16* Bl = smc + 3*128*CLD;

    int tid = threadIdx.x;
    int warp = tid >> 5;
    int wm = warp >> 1;
    int wn = warp & 1;
    int m0 = blockIdx.x*CBM;

    wmma::fragment<wmma::accumulator, 16, 16, 16, float> cf[2][4];
    #pragma unroll
    for (int i = 0; i < 2; i++)
        #pragma unroll
        for (int f = 0; f < 4; f++) wmma::fill_fragment(cf[i][f], 0.f);

    int row = tid >> 1, half = tid & 1;
    int m = m0 + row;
    bool rv = (m < M_CONV);
    int sb = 0, sh = 0, sw = 0;
    if (rv) {
        sb = m / NBINS;
        int sr = m - sb*NBINS;
        sh = sr / HTW;
        sw = sr - sh*HTW;
    }

    for (int r = 0; r < 9; r++) {
        int ry = r/3;
        int dy = ry - 1, dx = r - ry*3 - 1;
        int h2 = sh + dy, w2 = sw + dx;
        bool valid = rv && ((unsigned)h2 < HTH) && ((unsigned)w2 < HTW);
        size_t aoff = 0;
        if (valid) aoff = ((size_t)sb*NBINS + (size_t)h2*HTW + w2)*128 + half*64;
        size_t boff = ((size_t)(r*128 + row))*128 + half*64;

        __syncthreads();
        #pragma unroll
        for (int j = 0; j < 8; j++) {
            uint4 vh = make_uint4(0u,0u,0u,0u), vl = make_uint4(0u,0u,0u,0u);
            if (valid) {
                vh = *(const uint4*)(g_htb_hi + aoff + j*8);
                vl = *(const uint4*)(g_htb_lo + aoff + j*8);
            }
            int so = row*CLD + half*64 + j*8;
            *(uint4*)&Ah[so] = vh;
            *(uint4*)&Al[so] = vl;
            *(uint4*)&Bh[so] = *(const uint4*)(g_wb_hi + boff + j*8);
            *(uint4*)&Bl[so] = *(const uint4*)(g_wb_lo + boff + j*8);
        }
        __syncthreads();

        for (int ks = 0; ks < 8; ks++) {
            wmma::fragment<wmma::matrix_a, 16, 16, 16, __nv_bfloat16, wmma::row_major> a0h, a0l, a1h, a1l;
            wmma::load_matrix_sync(a0h, &Ah[(wm*32)*CLD + ks*16], CLD);
            wmma::load_matrix_sync(a1h, &Ah[(wm*32 + 16)*CLD + ks*16], CLD);
            wmma::load_matrix_sync(a0l, &Al[(wm*32)*CLD + ks*16], CLD);
            wmma::load_matrix_sync(a1l, &Al[(wm*32 + 16)*CLD + ks*16], CLD);
            #pragma unroll
            for (int f = 0; f < 4; f++) {
                int n0 = wn*64 + f*16;
                wmma::fragment<wmma::matrix_b, 16, 16, 16, __nv_bfloat16, wmma::row_major> bh, bl;
                wmma::load_matrix_sync(bh, &Bh[(ks*16)*CLD + n0], CLD);
                wmma::load_matrix_sync(bl, &Bl[(ks*16)*CLD + n0], CLD);
                wmma::mma_sync(cf[0][f], a0h, bh, cf[0][f]);
                wmma::mma_sync(cf[0][f], a0l, bh, cf[0][f]);
                wmma::mma_sync(cf[0][f], a0h, bl, cf[0][f]);
                wmma::mma_sync(cf[1][f], a1h, bh, cf[1][f]);
                wmma::mma_sync(cf[1][f], a1l, bh, cf[1][f]);
                wmma::mma_sync(cf[1][f], a1h, bl, cf[1][f]);
            }
        }
    }

    #pragma unroll
    for (int i = 0; i < 2; i++) {
        int mrow = m0 + wm*32 + i*16;
        if (mrow < M_CONV) {
            #pragma unroll
            for (int f = 0; f < 4; f++) {
                int n0 = wn*64 + f*16;
                wmma::store_matrix_sync(g_hc + (size_t)mrow*128 + n0, cf[i][f], 128, wmma::mem_row_major);
            }
        }
    }
}

// ================= 5) conv BN stats =================
__global__ void k_conv_stats1() {
    int chunk = blockIdx.x, c = threadIdx.x;
    size_t r0 = (size_t)chunk * ROWS_PER_CHUNK;
    float s = 0.f, q = 0.f;
    for (int i = 0; i < ROWS_PER_CHUNK; i++) {
        float v = g_hc[(r0 + i)*CC + c];
        s += v; q += v*v;
    }
    g_psum[chunk*CC + c] = s;
    g_psq[chunk*CC + c]  = q;
}
__global__ void k_conv_stats2(const float* __restrict__ gamma, const float* __restrict__ beta) {
    int c = threadIdx.x;
    float s = 0.f, q = 0.f;
    for (int i = 0; i < NCHUNK; i++) { s += g_psum[i*CC + c]; q += g_psq[i*CC + c]; }
    float inv = 1.f/(float)M_CONV;
    float m = s*inv;
    float var = q*inv - m*m;
    float r = rsqrtf(var + EPS_F);
    g_cscale[c] = gamma[c]*r;
    g_cbias[c]  = beta[c] - gamma[c]*m*r;
}

// ================= 6) sphere gather (writes to merged buffer) =================
__global__ void k_sphere(const int* __restrict__ ind, const int* __restrict__ sph_idx,
                         const float* __restrict__ sph_w, float* __restrict__ out, int S) {
    int j = blockIdx.x, b = blockIdx.y, c = threadIdx.x;
    int v = __ldg(&ind[b*S + j]);
    const float* hc = g_hc + (size_t)b*NBINS*CC;
    float sc = g_cscale[c], bi = g_cbias[c];
    float acc = 0.f;
    #pragma unroll
    for (int k = 0; k < KSPH; k++) {
        int bin = __ldg(&sph_idx[v*KSPH + k]);
        float w = __ldg(&sph_w[v*KSPH + k]);
        float x = sc*hc[(size_t)bin*CC + c] + bi;
        acc += w * fmaxf(x, 0.f);
    }
    out[((size_t)b*S + j)*CC + c] = acc;
}

// ================= 7) sconv merged across scales =================
__global__ void __launch_bounds__(256) k_sconv_all(const float* __restrict__ w_sc,
                                                   const float* __restrict__ b_sc) {
    __shared__ float Ws[128][64];
    __shared__ float xr[4][128];
    __shared__ float bs[64];
    int tid = threadIdx.x;
    int m0 = blockIdx.x * 16;
    int s = scale_of(m0);
    const float* w = w_sc + (size_t)s*64*128;
    for (int i = tid; i < 64*128; i += 256) {
        int o = i >> 7, c = i & 127;
        Ws[c][o] = w[i];
    }
    if (tid < 64) bs[tid] = b_sc[s*64 + tid];
    __syncthreads();
    int ty = tid >> 6, o = tid & 63;
    for (int rr = 0; rr < 16; rr += 4) {
        int m = m0 + rr + ty;
        xr[ty][o]      = g_sall[(size_t)m*128 + o];
        xr[ty][64 + o] = g_sall[(size_t)m*128 + 64 + o];
        __syncthreads();
        float acc = bs[o];
        #pragma unroll 8
        for (int c = 0; c < 128; c++) acc += xr[ty][c]*Ws[c][o];
        g_yall[(size_t)m*64 + o] = acc;
        __syncthreads();
    }
}

// ================= 7b) sconv BN stats merged =================
__global__ void k_sc_stats1_all() {
    int chunk = blockIdx.x, o = threadIdx.x;
    size_t r0 = (size_t)chunk * 64;
    float s = 0.f, q = 0.f;
    for (int i = 0; i < 64; i++) {
        float v = g_yall[(r0 + i)*64 + o];
        s += v; q += v*v;
    }
    g_p2s[chunk*64 + o] = s;
    g_p2q[chunk*64 + o] = q;
}
__global__ void k_sc_stats2_all(const float* __restrict__ gamma, const float* __restrict__ beta) {
    int s = blockIdx.x, o = threadIdx.x;
    int c0 = (s == 0) ? 0 : ((s == 1) ? 32 : 56);
    int c1 = (s == 0) ? 32 : ((s == 1) ? 56 : 62);
    int M  = (s == 0) ? 2048 : ((s == 1) ? 1536 : 384);
    float sm = 0.f, q = 0.f;
    for (int c = c0; c < c1; c++) { sm += g_p2s[c*64 + o]; q += g_p2q[c*64 + o]; }
    float inv = 1.f/(float)M;
    float mn = sm*inv;
    float var = q*inv - mn*mn;
    float r = rsqrtf(var + EPS_F);
    g_scs[s*64 + o] = gamma[s*64 + o]*r;
    g_scb[s*64 + o] = beta[s*64 + o] - gamma[s*64 + o]*mn*r;
}

// ================= 8) EdgeConv GEMM merged =================
__global__ void __launch_bounds__(256) k_gemm_all(const float* __restrict__ x,
                                                  const float* __restrict__ dgw,
                                                  const float* __restrict__ dgb,
                                                  int L) {
    __shared__ float Wc[64][64];
    __shared__ float Wn[64][64];
    __shared__ float xr[4][64];
    __shared__ float bs[64];
    int tid = threadIdx.x;
    int m0 = blockIdx.x * 16;
    int s = scale_of(m0);
    const float* W = dgw + ((size_t)s*4 + L)*128*64;
    for (int i = tid; i < 64*64; i += 256) {
        int c = i >> 6, o = i & 63;
        float wt = W[c*64 + o], wb = W[(64 + c)*64 + o];
        Wc[c][o] = wt - wb;
        Wn[c][o] = wb;
    }
    if (tid < 64) bs[tid] = dgb[(s*4 + L)*64 + tid];
    __syncthreads();
    int ty = tid >> 6, o = tid & 63;
    for (int rr = 0; rr < 16; rr += 4) {
        int m = m0 + rr + ty;
        float v = x[(size_t)m*64 + o];
        if (L == 0) v = fmaxf(g_scs[s*64 + o]*v + g_scb[s*64 + o], 0.f);
        xr[ty][o] = v;
        __syncthreads();
        float a0 = bs[o], a1 = 0.f;
        #pragma unroll 8
        for (int c = 0; c < 64; c++) {
            float xv = xr[ty][c];
            a0 += xv * Wc[c][o];
            a1 += xv * Wn[c][o];
        }
        g_zall[(size_t)m*128 + o]      = a0;
        g_zall[(size_t)m*128 + 64 + o] = a1;
        __syncthreads();
    }
}

// ================= 8b) EdgeConv combine merged =================
__global__ void k_combine_all(const int* __restrict__ e0, const int* __restrict__ e1,
                              const int* __restrict__ e2, float* __restrict__ xo) {
    int o  = threadIdx.x & 63;
    int jy = threadIdx.x >> 6;
    int g  = blockIdx.x*4 + jy;
    int base, n, bg, j;
    const int* eg;
    if (g < 2048)       { base = 0;    n = 1024; eg = e0; int m = g;        bg = m >> 10; j = m & 1023; }
    else if (g < 3584)  { base = 2048; n = 256;  eg = e1; int m = g - 2048; bg = m >> 8;  j = m & 255; }
    else                { base = 3584; n = 64;   eg = e2; int m = g - 3584; bg = m >> 6;  j = m & 63; }
    const int* ec = eg + (size_t)bg*2*n*8;
    const int* en = ec + n*8;
    const float* zb = g_zall + (size_t)(base + bg*n)*128;
    int e0i = j*8;
    float mx = 0.f;
    #pragma unroll
    for (int kk = 0; kk < 8; kk++) {
        int ci = __ldg(&ec[e0i + kk]);
        int ni = __ldg(&en[e0i + kk]);
        float v = zb[(size_t)ci*128 + o] + zb[(size_t)ni*128 + 64 + o];
        mx = fmaxf(mx, fmaxf(v, 0.f));
    }
    xo[(size_t)g*64 + o] = mx;
}

// ================= 9) head merged =================
__global__ void k_head_all(const float* __restrict__ x, const float* __restrict__ hw,
                           const float* __restrict__ hb) {
    int gw = (blockIdx.x*blockDim.x + threadIdx.x) >> 5;
    int lane = threadIdx.x & 31;
    if (gw >= MTOT) return;
    int s = scale_of(gw);
    const float* h = hw + s*64;
    float a = x[(size_t)gw*64 + lane]*h[lane] + x[(size_t)gw*64 + 32 + lane]*h[32 + lane];
    #pragma unroll
    for (int s2 = 16; s2 > 0; s2 >>= 1) a += __shfl_down_sync(0xffffffffu, a, s2);
    if (lane == 0) g_logit[gw] = a + hb[s];
}

// ================= 10) BCE =================
__global__ void k_bce(const float* __restrict__ logit, const int* __restrict__ target,
                      float* __restrict__ out, int M, int outIdx) {
    float sp = 0.f, sn = 0.f, cp = 0.f, cn = 0.f;
    for (int i = threadIdx.x; i < M; i += 256) {
        float z = logit[i];
        float t = (float)target[i];
        float l = fmaxf(z, 0.f) - z*t + log1pf(expf(-fabsf(z)));
        if (t > 0.5f) { sp += l; cp += 1.f; } else { sn += l; cn += 1.f; }
    }
    __shared__ float r0[256], r1[256], r2[256], r3[256];
    r0[threadIdx.x]=sp; r1[threadIdx.x]=sn; r2[threadIdx.x]=cp; r3[threadIdx.x]=cn;
    __syncthreads();
    for (int st = 128; st > 0; st >>= 1) {
        if (threadIdx.x < st) {
            r0[threadIdx.x]+=r0[threadIdx.x+st]; r1[threadIdx.x]+=r1[threadIdx.x+st];
            r2[threadIdx.x]+=r2[threadIdx.x+st]; r3[threadIdx.x]+=r3[threadIdx.x+st];
        }
        __syncthreads();
    }
    if (threadIdx.x == 0) {
        out[outIdx]   = r0[0] / fmaxf(r2[0], 1.f);
        out[outIdx+1] = r1[0] / fmaxf(r3[0], 1.f);
    }
}

// ================= 11) preds =================
__global__ void k_preds(float* __restrict__ out) {
    int i = blockIdx.x*blockDim.x + threadIdx.x;
    if (i >= 3968) return;
    float z; int b, col;
    if (i < 2048) {
        b = i >> 10; col = i & 1023;
        z = g_logit[i];
    } else if (i < 3584) {
        int m = i - 2048;
        int bg = m >> 8, j = m & 255;
        b = bg/3; int v = bg - b*3;
        col = 1024 + v*256 + j;
        z = g_logit[2048 + m];
    } else {
        int m = i - 3584;
        int bg = m >> 6, j = m & 63;
        b = bg/3; int v = bg - b*3;
        col = 1792 + v*64 + j;
        z = g_logit[3584 + m];
    }
    out[6 + b*1984 + col] = 1.f/(1.f + expf(-z));
}

// ================= launch =================
extern "C" void kernel_launch(void* const* d_in, const int* in_sizes, int n_in,
                              void* d_out, int out_size) {
    const float* image     = (const float*)d_in[0];
    const float* bn_gamma  = (const float*)d_in[1];
    const float* bn_beta   = (const float*)d_in[2];
    const int*   ht_idx    = (const int*)  d_in[3];
    const float* ht_w      = (const float*)d_in[4];
    const float* w_htconv  = (const float*)d_in[5];
    const float* htbn_g    = (const float*)d_in[6];
    const float* htbn_b    = (const float*)d_in[7];
    const int*   sph_idx   = (const int*)  d_in[8];
    const float* sph_w     = (const float*)d_in[9];
    const float* w_sc      = (const float*)d_in[10];
    const float* b_sc      = (const float*)d_in[11];
    const float* scbn_g    = (const float*)d_in[12];
    const float* scbn_b    = (const float*)d_in[13];
    const float* dgcn_w    = (const float*)d_in[14];
    const float* dgcn_b    = (const float*)d_in[15];
    const float* dgcn_hw   = (const float*)d_in[16];
    const float* dgcn_hb   = (const float*)d_in[17];
    const int*   ind0      = (const int*)  d_in[18];
    const int*   ind1      = (const int*)  d_in[19];
    const int*   ind2      = (const int*)  d_in[20];
    const int*   edge0     = (const int*)  d_in[21];
    const int*   edge1     = (const int*)  d_in[22];
    const int*   edge2     = (const int*)  d_in[23];
    const int*   target0   = (const int*)  d_in[24];
    const int*   target1   = (const int*)  d_in[25];
    const int*   target2   = (const int*)  d_in[26];
    float* out = (float*)d_out;

    cudaFuncSetAttribute(k_conv_wmma, cudaFuncAttributeMaxDynamicSharedMemorySize, CONV_SMEM);

    k_img_stats<<<CC, 256>>>(image, bn_gamma, bn_beta);
    k_bn_transpose<<<dim3(NPIX/32, CC/32, BB), dim3(32,8)>>>(image);
    k_wsplit<<<(1152*128 + 255)/256, 256>>>(w_htconv);
    k_hough<<<dim3(NBINS, BB), CC>>>(ht_idx, ht_w);
    k_conv_wmma<<<CONV_GRID, 256, CONV_SMEM>>>();
    k_conv_stats1<<<NCHUNK, CC>>>();
    k_conv_stats2<<<1, CC>>>(htbn_g, htbn_b);

    float* g_sallp; cudaGetSymbolAddress((void**)&g_sallp, g_sall);
    float* g_yallp; cudaGetSymbolAddress((void**)&g_yallp, g_yall);
    float* g_tallp; cudaGetSymbolAddress((void**)&g_tallp, g_tall);
    float* g_logitp; cudaGetSymbolAddress((void**)&g_logitp, g_logit);

    k_sphere<<<dim3(NN0,   BB), CC>>>(ind0, sph_idx, sph_w, g_sallp, NN0);
    k_sphere<<<dim3(3*NN1, BB), CC>>>(ind1, sph_idx, sph_w, g_sallp + 2048*128, 3*NN1);
    k_sphere<<<dim3(3*NN2, BB), CC>>>(ind2, sph_idx, sph_w, g_sallp + 3584*128, 3*NN2);

    k_sconv_all<<<MTOT/16, 256>>>(w_sc, b_sc);
    k_sc_stats1_all<<<MTOT/64, 64>>>();
    k_sc_stats2_all<<<3, 64>>>(scbn_g, scbn_b);

    float* xin = g_yallp;
    for (int L = 0; L < 4; L++) {
        k_gemm_all<<<MTOT/16, 256>>>(xin, dgcn_w, dgcn_b, L);
        float* xout = (L & 1) ? g_yallp : g_tallp;
        k_combine_all<<<MTOT/4, 256>>>(edge0, edge1, edge2, xout);
        xin = xout;
    }
    k_head_all<<<(MTOT*32 + 255)/256, 256>>>(xin, dgcn_hw, dgcn_hb);

    const int M0 = 2048, M1 = 1536, M2 = 384;
    k_bce<<<1, 256>>>(g_logitp,           target0, out, M0, 0);
    k_bce<<<1, 256>>>(g_logitp + M0,      target1, out, M1, 2);
    k_bce<<<1, 256>>>(g_logitp + M0 + M1, target2, out, M2, 4);
    k_preds<<<(3968 + 255)/256, 256>>>(out);
    (void)in_sizes; (void)n_in; (void)out_size;
}